// round 1
// baseline (speedup 1.0000x reference)
#include <cuda_runtime.h>

// Problem constants
#define B_  16
#define C_  64
#define H_  224
#define W_  224
#define O_  128
#define PH_ 16
#define OH_ 222   // H - 3 + 1
#define OW_ 222

// Intermediate: s[b,h,w] = sum_c (x[b,c,h,w]*pw[c,h%16,w%16] + pb[c,h%16,w%16])
__device__ float g_s[(size_t)B_ * H_ * W_];

// -------- Kernel 1: channel reduction --------
// grid.x = B*H (one row per block), block = 224 threads (one per w)
__global__ __launch_bounds__(224) void k1_reduce_c(
    const float* __restrict__ x,
    const float* __restrict__ pw,
    const float* __restrict__ pb)
{
    const int row = blockIdx.x;          // 0 .. B*H-1
    const int b = row / H_;
    const int h = row % H_;
    const int hh = h & (PH_ - 1);

    __shared__ float pws[C_ * PH_];      // pw[c][hh][ww] -> pws[c*16+ww]
    __shared__ float bsum[PH_];          // sum_c pb[c][hh][ww]

    const int t = threadIdx.x;           // 0..223

    // stage pw slice for this intra-patch row
    for (int idx = t; idx < C_ * PH_; idx += blockDim.x) {
        int c  = idx >> 4;
        int ww = idx & 15;
        pws[idx] = pw[c * (PH_ * PH_) + hh * PH_ + ww];
    }
    if (t < PH_) {
        float s = 0.f;
        #pragma unroll 8
        for (int c = 0; c < C_; c++)
            s += pb[c * (PH_ * PH_) + hh * PH_ + t];
        bsum[t] = s;
    }
    __syncthreads();

    const int w  = t;
    const int ww = w & (PH_ - 1);
    const float* xp = x + ((size_t)b * C_ * H_ + h) * W_ + w;

    float acc = 0.f;
    #pragma unroll 8
    for (int c = 0; c < C_; c++) {
        acc = fmaf(__ldg(xp + (size_t)c * (H_ * W_)), pws[c * PH_ + ww], acc);
    }
    g_s[((size_t)b * H_ + h) * W_ + w] = acc + bsum[ww];
}

// -------- Kernel 2: 3x3 conv of s against 128 shared-channel filters --------
// grid.x = B*OH (one output row), grid.y = 8 (groups of 16 output channels)
// block = 224 threads (j = 0..221 produce output, all 224 stage smem)
#define OCG 16
__global__ __launch_bounds__(224) void k2_conv3x3(
    const float* __restrict__ comp,
    float* __restrict__ out)
{
    const int r  = blockIdx.x;           // 0 .. B*OH-1
    const int b  = r / OH_;
    const int i  = r % OH_;
    const int o0 = blockIdx.y * OCG;

    __shared__ float srow[3][W_];
    __shared__ float csh[OCG * 9];

    const int t = threadIdx.x;           // 0..223

    const float* sp = g_s + ((size_t)b * H_ + i) * W_;
    srow[0][t] = sp[t];
    srow[1][t] = sp[W_ + t];
    srow[2][t] = sp[2 * W_ + t];
    if (t < OCG * 9) csh[t] = comp[o0 * 9 + t];
    __syncthreads();

    if (t < OW_) {
        float v[9];
        #pragma unroll
        for (int dh = 0; dh < 3; dh++)
            #pragma unroll
            for (int dw = 0; dw < 3; dw++)
                v[dh * 3 + dw] = srow[dh][t + dw];

        size_t base = (((size_t)b * O_ + o0) * OH_ + i) * OW_ + t;
        #pragma unroll
        for (int k = 0; k < OCG; k++) {
            float acc = 0.f;
            #pragma unroll
            for (int q = 0; q < 9; q++)
                acc = fmaf(csh[k * 9 + q], v[q], acc);
            out[base + (size_t)k * (OH_ * OW_)] = acc;
        }
    }
}

extern "C" void kernel_launch(void* const* d_in, const int* in_sizes, int n_in,
                              void* d_out, int out_size)
{
    const float* x    = (const float*)d_in[0];
    const float* pw   = (const float*)d_in[1];
    const float* pb   = (const float*)d_in[2];
    const float* comp = (const float*)d_in[3];
    float* out = (float*)d_out;

    k1_reduce_c<<<B_ * H_, 224>>>(x, pw, pb);
    dim3 g2(B_ * OH_, O_ / OCG);
    k2_conv3x3<<<g2, 224>>>(comp, out);
}

// round 2
// speedup vs baseline: 1.0924x; 1.0924x over previous
#include <cuda_runtime.h>

// Problem constants
#define B_  16
#define C_  64
#define H_  224
#define W_  224
#define O_  128
#define PH_ 16
#define OH_ 222   // H - 3 + 1
#define OW_ 222

// Intermediate: s[b,h,w] = sum_c (x[b,c,h,w]*pw[c,h%16,w%16] + pb[c,h%16,w%16])
__device__ float g_s[(size_t)B_ * H_ * W_];

// ================= Kernel 1: channel reduction (float4) =================
// block = 224 threads = 4 rows x 56 float4-columns; grid = B*H/4 = 896
__global__ __launch_bounds__(224) void k1_reduce_c(
    const float* __restrict__ x,
    const float* __restrict__ pw,
    const float* __restrict__ pb)
{
    const int blk = blockIdx.x;              // 0..895
    const int b   = blk / (H_ / 4);          // H_/4 = 56
    const int h0  = (blk % (H_ / 4)) * 4;

    __shared__ float4 pws[4][C_][4];         // [row][c][w4]  16 KB
    __shared__ float4 bsum[4][4];            // [row][w4]

    const int t = threadIdx.x;

    // stage pw for the 4 rows (each has its own hh)
    const float4* pw4 = (const float4*)pw;
    for (int idx = t; idx < 4 * C_ * 4; idx += 224) {
        int rr = idx >> 8;                   // / 256
        int c  = (idx >> 2) & (C_ - 1);
        int w4 = idx & 3;
        int hh = (h0 + rr) & (PH_ - 1);
        pws[rr][c][w4] = pw4[c * 64 + hh * 4 + w4];
    }
    // bias sums (16 float4)
    if (t < 16) {
        int rr = t >> 2, w4 = t & 3;
        int hh = (h0 + rr) & (PH_ - 1);
        const float4* pb4 = (const float4*)pb;
        float4 s = make_float4(0.f, 0.f, 0.f, 0.f);
        #pragma unroll 8
        for (int c = 0; c < C_; c++) {
            float4 v = pb4[c * 64 + hh * 4 + w4];
            s.x += v.x; s.y += v.y; s.z += v.z; s.w += v.w;
        }
        bsum[rr][w4] = s;
    }
    __syncthreads();

    const int r      = t / 56;               // row in block
    const int lane_w = t % 56;               // float4 column
    const int w4     = lane_w & 3;           // intra-patch float4 col
    const int h      = h0 + r;

    const float4* xp = (const float4*)x + ((size_t)b * C_ * H_ + h) * 56 + lane_w;

    float4 acc = bsum[r][w4];
    #pragma unroll 8
    for (int c = 0; c < C_; c++) {
        float4 xv = __ldg(xp + (size_t)c * (H_ * 56));
        float4 wv = pws[r][c][w4];
        acc.x = fmaf(xv.x, wv.x, acc.x);
        acc.y = fmaf(xv.y, wv.y, acc.y);
        acc.z = fmaf(xv.z, wv.z, acc.z);
        acc.w = fmaf(xv.w, wv.w, acc.w);
    }
    ((float4*)g_s)[((size_t)b * H_ + h) * 56 + lane_w] = acc;
}

// ================= Kernel 2: 3x3 conv, 128 shared-channel filters =================
// block = 224 threads = 2 output rows x 112 column-pairs
// grid.x = B * OH/2 = 16*111, grid.y = O/OCG = 4   (OCG = 32)
#define OCG 32
__global__ __launch_bounds__(224) void k2_conv3x3(
    const float* __restrict__ comp,
    float* __restrict__ out)
{
    const int gx = blockIdx.x;
    const int b  = gx / (OH_ / 2);           // OH_/2 = 111
    const int i0 = (gx % (OH_ / 2)) * 2;
    const int o0 = blockIdx.y * OCG;

    __shared__ float srow[4][W_];            // input rows i0..i0+3 (3.5 KB)
    __shared__ float csh[OCG * 12];          // weights padded to 12 floats (1.5 KB)

    const int t = threadIdx.x;

    // stage 4 s-rows (coalesced)
    const float* sp = g_s + ((size_t)b * H_ + i0) * W_;
    #pragma unroll
    for (int k = 0; k < 4; k++)
        srow[k][t] = sp[k * W_ + t];
    // stage weights: OCG*9 values into 12-float-padded rows
    for (int idx = t; idx < OCG * 9; idx += 224) {
        int k = idx / 9, m = idx % 9;
        csh[k * 12 + m] = comp[(o0 + k) * 9 + m];
    }
    __syncthreads();

    const int r  = t / 112;                  // output row within block (0/1)
    const int q  = t % 112;                  // column pair index
    if (q >= 111) return;                    // 111 pairs cover 222 cols
    const int j0 = q * 2;
    const int i  = i0 + r;

    // gather 3 rows x 4 cols into registers (float2 LDS, 8B aligned)
    float2 va[3], vb[3];
    #pragma unroll
    for (int d = 0; d < 3; d++) {
        va[d] = *(const float2*)&srow[r + d][j0];
        vb[d] = *(const float2*)&srow[r + d][j0 + 2];
    }

    const float4* csh4 = (const float4*)csh;
    size_t base = (((size_t)b * O_ + o0) * OH_ + i) * OW_ + j0;

    #pragma unroll 8
    for (int k = 0; k < OCG; k++) {
        float4 w0 = csh4[k * 3 + 0];         // w[0..3]
        float4 w1 = csh4[k * 3 + 1];         // w[4..7]
        float4 w2 = csh4[k * 3 + 2];         // w[8], pad

        float ax, ay;
        ax = w0.x * va[0].x; ay = w0.x * va[0].y;
        ax = fmaf(w0.y, va[0].y, ax); ay = fmaf(w0.y, vb[0].x, ay);
        ax = fmaf(w0.z, vb[0].x, ax); ay = fmaf(w0.z, vb[0].y, ay);

        ax = fmaf(w0.w, va[1].x, ax); ay = fmaf(w0.w, va[1].y, ay);
        ax = fmaf(w1.x, va[1].y, ax); ay = fmaf(w1.x, vb[1].x, ay);
        ax = fmaf(w1.y, vb[1].x, ax); ay = fmaf(w1.y, vb[1].y, ay);

        ax = fmaf(w1.z, va[2].x, ax); ay = fmaf(w1.z, va[2].y, ay);
        ax = fmaf(w1.w, va[2].y, ax); ay = fmaf(w1.w, vb[2].x, ay);
        ax = fmaf(w2.x, vb[2].x, ax); ay = fmaf(w2.x, vb[2].y, ay);

        *(float2*)(out + base + (size_t)k * (OH_ * OW_)) = make_float2(ax, ay);
    }
}

extern "C" void kernel_launch(void* const* d_in, const int* in_sizes, int n_in,
                              void* d_out, int out_size)
{
    const float* x    = (const float*)d_in[0];
    const float* pw   = (const float*)d_in[1];
    const float* pb   = (const float*)d_in[2];
    const float* comp = (const float*)d_in[3];
    float* out = (float*)d_out;

    k1_reduce_c<<<B_ * (H_ / 4), 224>>>(x, pw, pb);
    dim3 g2(B_ * (OH_ / 2), O_ / OCG);
    k2_conv3x3<<<g2, 224>>>(comp, out);
}